// round 13
// baseline (speedup 1.0000x reference)
#include <cuda_runtime.h>
#include <cstdint>

// Fused feature replacement — single-wave, rolling-window pipeline (wrap-fixed).
//
// Layout: [B=32, C=512, HW=784] fp32 -> 196 float4 per (b,c) slice.
// Block tile = 4096 contiguous float4s (16 per thread, 256 threads);
// 3,211,264 / 4096 = 784 blocks EXACTLY = one wave on 148 SMs at 6 blocks/SM.
// A tile spans <= 22 consecutive (b,c) slices and MAY cross a batch boundary
// (100,352 / 4096 = 24.5), so the mask build must be wrap-aware:
// slice at window offset rel has channel (c_base + rel) & 511, hence index
// channel c maps to rel = (c - c_base) & 511; mark if rel < 32.
//
// Rolling 6-deep load window pinned by volatile asm:
//   L0..L5 ; {S0 L6} {S1 L7} ... {S9 L15} ; S10..S15
// Loads: ld.global.nc. Stores: st.global.cs (R5 vs R7 proved .cs > .wt;
// keeps the 103 MB of inputs L2-resident across graph replays).

__global__ void __launch_bounds__(256, 6)
fused_replace_kernel(const float4* __restrict__ out_src,
                     const float4* __restrict__ feat_src,
                     float4* __restrict__ dst,
                     const int* __restrict__ idx,
                     int num_replace)
{
    __shared__ unsigned mword;

    const int tid    = threadIdx.x;
    const int B0     = blockIdx.x << 12;     // first float4 index of this tile
    const int s_lo   = B0 / 196;             // first (b,c) slice index
    const int c_base = s_lo & 511;           // its channel (C=512, pow2)

    if (tid == 0) mword = 0u;
    __syncthreads();

    // Wrap-aware mask: rel = (c - c_base) mod 512; window uses rel 0..21.
    if (tid < num_replace) {                 // indices are int32 (JAX x64 off)
        int r = (idx[tid] - c_base) & 511;
        if (r < 32) atomicOr(&mword, 1u << r);
    }
    for (int t = tid + 256; t < num_replace; t += 256) {   // general tail
        int r = (idx[t] - c_base) & 511;
        if (r < 32) atomicOr(&mword, 1u << r);
    }
    __syncthreads();

    const unsigned bmask = mword;            // one LDS broadcast, then pure ALU
    const int i0 = B0 + tid;

    float4 v[6];                             // rolling window: slot k % 6

#define LOADK(k)                                                               \
    {                                                                          \
        int i   = i0 + ((k) << 8);                                             \
        int rel = i / 196 - s_lo;            /* 0..21 in this tile */          \
        const float4* p =                                                      \
            (((bmask >> rel) & 1u) ? feat_src : out_src) + i;                  \
        asm volatile("ld.global.nc.v4.f32 {%0,%1,%2,%3}, [%4];"                \
                     : "=f"(v[(k) % 6].x), "=f"(v[(k) % 6].y),                 \
                       "=f"(v[(k) % 6].z), "=f"(v[(k) % 6].w)                  \
                     : "l"(p));                                                \
    }

#define STORK(k)                                                               \
    {                                                                          \
        const float4* q = dst + i0 + ((k) << 8);                               \
        asm volatile("st.global.cs.v4.f32 [%0], {%1,%2,%3,%4};"                \
                     :: "l"(q),                                                \
                        "f"(v[(k) % 6].x), "f"(v[(k) % 6].y),                  \
                        "f"(v[(k) % 6].z), "f"(v[(k) % 6].w)                   \
                     : "memory");                                              \
    }

    // Prologue: fill the 6-deep window.
    LOADK(0) LOADK(1) LOADK(2) LOADK(3) LOADK(4) LOADK(5)
    // Steady state: store the oldest slot, immediately refill it.
    STORK(0)  LOADK(6)
    STORK(1)  LOADK(7)
    STORK(2)  LOADK(8)
    STORK(3)  LOADK(9)
    STORK(4)  LOADK(10)
    STORK(5)  LOADK(11)
    STORK(6)  LOADK(12)
    STORK(7)  LOADK(13)
    STORK(8)  LOADK(14)
    STORK(9)  LOADK(15)
    // Drain.
    STORK(10) STORK(11) STORK(12) STORK(13) STORK(14) STORK(15)

#undef LOADK
#undef STORK
}

extern "C" void kernel_launch(void* const* d_in, const int* in_sizes, int n_in,
                              void* d_out, int out_size)
{
    const float* out_t  = (const float*)d_in[0];   // output             [32,512,28,28] f32
    const float* feat_t = (const float*)d_in[1];   // matryoshka_features[32,512,28,28] f32
    const int*   idx    = (const int*)d_in[2];     // indices (int32)    [256]

    const int num_replace = in_sizes[2];           // 256
    const int n4 = out_size / 4;                   // 3,211,264 float4s
    const int blocks = n4 >> 12;                   // 784 (exact) = one wave

    fused_replace_kernel<<<blocks, 256>>>((const float4*)out_t,
                                          (const float4*)feat_t,
                                          (float4*)d_out,
                                          idx, num_replace);
}

// round 15
// speedup vs baseline: 1.0217x; 1.0217x over previous
#include <cuda_runtime.h>
#include <cstdint>

// Fused feature replacement, forced-MLP version — FINAL (measured 14.6 us, R5).
//
// Layout: [B=32, C=512, HW=784] fp32 -> 196 float4 per (b,c) slice.
// Block tile = 2048 contiguous float4s (8 per thread, 256 threads).
// 3,211,264 / 2048 = 1568 blocks exactly -> no bounds guards needed.
// A tile spans <= 11 consecutive channels (2048 divides a batch: 100352/2048
// = 49, so no batch crossing) -> 16-entry shared mask.
//
// Why this is the floor: per replay the kernel must move 51.4 MB of reads
// (each element reads exactly one source) + 51.4 MB of writes through L2
// (L1 is flushed per launch), i.e. 102.8 MB of mandatory LTS traffic. At
// 14.6 us that is ~7 TB/s ~= the LTS throughput cap at unramped clocks.
// Three structurally different schedules (phase-batched, sw-pipelined,
// single-wave) all land in 14.6-15.0 us, confirming LTS-bound.
//
// Policies (empirically settled): plain ld.global loads; st.global.cs stores
// (.cs 14.6us beat .wt 18.3us; evict-first output keeps the read set and
// write set co-resident in ~120 MB L2 -> near-zero steady-state DRAM).

__global__ void __launch_bounds__(256)
fused_replace_kernel(const float4* __restrict__ out_src,
                     const float4* __restrict__ feat_src,
                     float4* __restrict__ dst,
                     const int* __restrict__ idx,
                     int num_replace)
{
    __shared__ int smask[16];

    const int tid  = threadIdx.x;
    const int B0   = blockIdx.x << 11;       // first float4 index of this tile
    const int s_lo = B0 / 196;               // first (b,c) slice index
    const int c_base = s_lo & 511;           // its channel (C=512, pow2)

    if (tid < 16) smask[tid] = 0;
    __syncthreads();

    // Mark replaced channels falling inside this tile's <=11-channel window.
    if (tid < num_replace) {
        int r = idx[tid] - c_base;           // indices are int32 (JAX x64 off)
        if (r >= 0 && r < 16) smask[r] = 1;
    }
    for (int t = tid + 256; t < num_replace; t += 256) {   // general tail
        int r = idx[t] - c_base;
        if (r >= 0 && r < 16) smask[r] = 1;
    }
    __syncthreads();

    const int i0 = B0 + tid;

    // Phase 1: resolve the 8 source addresses.
    const float4* src[8];
#pragma unroll
    for (int k = 0; k < 8; k++) {
        int i   = i0 + (k << 8);
        int rel = i / 196 - s_lo;            // 0..10 within this tile
        src[k] = (smask[rel] ? feat_src : out_src) + i;
    }

    // Phase 2: eight independent 128-bit loads, issued back-to-back (MLP=8).
    float4 v[8];
#pragma unroll
    for (int k = 0; k < 8; k++) {
        asm volatile("ld.global.v4.f32 {%0,%1,%2,%3}, [%4];"
                     : "=f"(v[k].x), "=f"(v[k].y), "=f"(v[k].z), "=f"(v[k].w)
                     : "l"(src[k]));
    }

    // Phase 3: evict-first streaming stores.
#pragma unroll
    for (int k = 0; k < 8; k++) {
        __stcs(dst + i0 + (k << 8), v[k]);
    }
}

extern "C" void kernel_launch(void* const* d_in, const int* in_sizes, int n_in,
                              void* d_out, int out_size)
{
    const float* out_t  = (const float*)d_in[0];   // output             [32,512,28,28] f32
    const float* feat_t = (const float*)d_in[1];   // matryoshka_features[32,512,28,28] f32
    const int*   idx    = (const int*)d_in[2];     // indices (int32)    [256]

    const int num_replace = in_sizes[2];           // 256
    const int n4 = out_size / 4;                   // 3,211,264 float4s
    const int blocks = n4 >> 11;                   // 1568 (exact)

    fused_replace_kernel<<<blocks, 256>>>((const float4*)out_t,
                                          (const float4*)feat_t,
                                          (float4*)d_out,
                                          idx, num_replace);
}